// round 12
// baseline (speedup 1.0000x reference)
#include <cuda_runtime.h>
#include <cuda_bf16.h>
#include <stdint.h>
#include <math.h>

#define NG 8
#define LG 1024
#define NH 8
#define HD 16
#define DS 64
#define NB 64
#define NE 131072
#define NN_NODES 8192
#define MSZ (64ULL * 1024 * 1024)

typedef __nv_bfloat16 bf16;

__device__ float g_S[MSZ];
__device__ float g_G[8ULL * 1024 * 1024];
// each logical matrix: hi plane at [0, MSZ), lo plane at [MSZ, 2*MSZ)
__device__ bf16 g_La[2 * MSZ], g_LaT[2 * MSZ];
__device__ bf16 g_Lb[2 * MSZ], g_LbT[2 * MSZ];
__device__ bf16 g_Oa[2 * MSZ], g_Ob[2 * MSZ];
__device__ float g_e0[NH * NN_NODES];
__device__ float g_e1[NH * NN_NODES];
__device__ float g_dummy[NH * NN_NODES];
__device__ float g_w[NH * NN_NODES];

// ---------------- helpers ----------------
__device__ __forceinline__ uint32_t smem_u32(const void* p) {
    uint32_t a;
    asm("{ .reg .u64 t; cvta.to.shared.u64 t, %1; cvt.u32.u64 %0, t; }" : "=r"(a) : "l"(p));
    return a;
}
#define CP16(dst, src) asm volatile("cp.async.cg.shared.global [%0], [%1], 16;" :: "r"(dst), "l"(src) : "memory")
#define CP_COMMIT()    asm volatile("cp.async.commit_group;" ::: "memory")
#define CP_WAIT1()     asm volatile("cp.async.wait_group 1;" ::: "memory")
#define CP_WAIT0()     asm volatile("cp.async.wait_group 0;" ::: "memory")

#define LDSM4(r, addr) \
    asm volatile("ldmatrix.sync.aligned.m8n8.x4.shared.b16 {%0,%1,%2,%3}, [%4];" \
        : "=r"((r)[0]), "=r"((r)[1]), "=r"((r)[2]), "=r"((r)[3]) : "r"(addr))

#define MMA16816(d, a, b0, b1) \
    asm volatile("mma.sync.aligned.m16n8k16.row.col.f32.bf16.bf16.f32 " \
        "{%0,%1,%2,%3}, {%4,%5,%6,%7}, {%8,%9}, {%0,%1,%2,%3};" \
        : "+f"((d)[0]), "+f"((d)[1]), "+f"((d)[2]), "+f"((d)[3]) \
        : "r"((a)[0]), "r"((a)[1]), "r"((a)[2]), "r"((a)[3]), "r"(b0), "r"(b1))

__device__ __forceinline__ float bf_lo(uint32_t u) { return __bfloat162float(__ushort_as_bfloat16((unsigned short)(u & 0xFFFF))); }
__device__ __forceinline__ float bf_hi(uint32_t u) { return __bfloat162float(__ushort_as_bfloat16((unsigned short)(u >> 16))); }
__device__ __forceinline__ void split_bf16(float v, bf16& h, bf16& l) {
    h = __float2bfloat16(v);
    l = __float2bfloat16(v - __bfloat162float(h));
}
__device__ __forceinline__ uint32_t pack2(bf16 a, bf16 b) {
    return ((uint32_t)__bfloat16_as_ushort(b) << 16) | __bfloat16_as_ushort(a);
}
__device__ __forceinline__ float softplusf(float x) { return (x > 15.f) ? x : log1pf(expf(x)); }

// swizzled offset inside a 128-row x 64B operand block: row r, 16B-chunk c (0..3)
__device__ __forceinline__ uint32_t swz(int r, int c) {
    return (uint32_t)(r * 64 + ((c ^ (r >> 1)) & 3) * 16);
}

// ---------------- fused zero + per-node prep ----------------
__global__ void k_zeronode(const float* __restrict__ dt, const float* __restrict__ dtb,
                           float* __restrict__ S) {
    int gid = blockIdx.x * blockDim.x + threadIdx.x;
    if (gid < NN_NODES * NH) {
        int n = gid >> 3, h = gid & 7;
        float b = dtb[h];
        const float* row = dt + (size_t)n * (NH * 4) + h * 4;
        g_e0[h * NN_NODES + n] = -softplusf(row[0] + b);
        g_e1[h * NN_NODES + n] = -softplusf(row[1] + b);
        g_dummy[h * NN_NODES + n] = expf(-softplusf(row[2] + b));
        g_w[h * NN_NODES + n] = row[3];
    }
    size_t i = (size_t)gid * 4;
    size_t st = (size_t)gridDim.x * blockDim.x * 4;
    float4 z = make_float4(0.f, 0.f, 0.f, 0.f);
    for (; i < MSZ; i += st) *(float4*)(S + i) = z;
}

// ---------------- edge scatter ----------------
__global__ void k_scatter(const int* __restrict__ ei) {
    int idx = blockIdx.x * blockDim.x + threadIdx.x;
    if (idx >= NE * NH) return;
    int e = idx >> 3, h = idx & 7;
    int s = ei[e], d = ei[NE + e];
    int b = s >> 10, sl = s & 1023, dl = d & 1023;
    float v = expf(0.5f * (g_e0[h * NN_NODES + s] + g_e1[h * NN_NODES + d]));
    atomicAdd(&g_S[(((size_t)(b * NH + h)) * LG + sl) * LG + dl], v);
}

// ---------------- fused norm + prep ----------------
__global__ void __launch_bounds__(256) k_normprep() {
    __shared__ float snrm[32];
    __shared__ float t[32][33];
    int bh = blockIdx.y;
    int j0 = blockIdx.x * 32;
    int b = bh >> 3, h = bh & 7;
    size_t off = (size_t)bh << 20;
    int tid = threadIdx.x;
    int wid = tid >> 5, lane = tid & 31;

    #pragma unroll
    for (int rr = 0; rr < 4; rr++) {
        int jj = wid * 4 + rr;
        const float* row = g_S + off + (size_t)(j0 + jj) * LG;
        float s = 0.f;
        for (int i = lane; i < LG; i += 32) s += row[i];
        #pragma unroll
        for (int o = 16; o; o >>= 1) s += __shfl_xor_sync(0xFFFFFFFFu, s, o);
        if (lane == 0)
            snrm[jj] = 1.f / (s + g_dummy[h * NN_NODES + b * LG + j0 + jj] + 0.1f);
    }
    __syncthreads();

    int tx = tid & 31, ty = tid >> 5;   // (32, 8)
    for (int i0 = 0; i0 < LG; i0 += 32) {
        #pragma unroll
        for (int k = 0; k < 4; k++) {
            int jj = ty + k * 8;
            float v = g_S[off + (size_t)(j0 + jj) * LG + i0 + tx];
            t[jj][tx] = v;
            float mt = v * snrm[jj];
            size_t o = off + (size_t)(j0 + jj) * LG + i0 + tx;
            bf16 hh, ll; split_bf16(mt, hh, ll);
            g_LaT[o] = hh; g_LaT[MSZ + o] = ll;
        }
        __syncthreads();
        #pragma unroll
        for (int k = 0; k < 4; k++) {
            int i = i0 + ty + k * 8;
            int j = j0 + tx;
            float v = t[tx][ty + k * 8] * snrm[tx];
            size_t o = off + (size_t)i * LG + j;
            bf16 hh, ll; split_bf16(v, hh, ll);
            g_La[o] = hh; g_La[MSZ + o] = ll;
            float w = v + ((i == j) ? 1.f : 0.f);
            split_bf16(w, hh, ll);
            g_Oa[o] = hh; g_Oa[MSZ + o] = ll;
        }
        __syncthreads();
    }
}

// ---------------- HMMA batched GEMM body: C = A@B (+Add), split bf16 x3 ----------------
// Tile 128x128, warp tile 64x32, KC=32, 3-stage, XOR-swizzled 64B rows, 1 sync/kt.
// kt unrolled by 3 (compile-time stage bases); prefetch split A/B across kh halves.
// A-fragment software pipeline: hi pass then lo pass, each with 2-deep frag double buffer.
#define STAGE_SZ 32768
#define MMA_SMEM (3 * STAGE_SZ)

__device__ __forceinline__ void mma_body(const bf16* __restrict__ A,
                                         const bf16* __restrict__ B,
                                         bf16* __restrict__ C,
                                         const bf16* __restrict__ Add,
                                         bf16* __restrict__ T,
                                         char* dsm, int zb,
                                         int bx, int by, int tid) {
    size_t moff = (size_t)zb << 20;
    A += moff; B += moff; C += moff;
    if (Add) Add += moff;
    if (T) T += moff;
    int row0 = by * 128, col0 = bx * 128;

    uint32_t sm0 = smem_u32(dsm);
    int wid = tid >> 5, lane = tid & 31;
    int wm = (wid >> 2) * 64, wn = (wid & 3) * 32;

    float acc[4][4][4];
    #pragma unroll
    for (int i = 0; i < 4; i++)
        #pragma unroll
        for (int j = 0; j < 4; j++)
            #pragma unroll
            for (int k = 0; k < 4; k++) acc[i][j][k] = 0.f;

    const int r0c = tid >> 2, c0c = tid & 3;

    auto preloadA = [&](int kt, uint32_t base) {
        #pragma unroll
        for (int q = 0; q < 2; q++) {
            int r = r0c + q * 64;
            uint32_t so = swz(r, c0c);
            size_t go = (size_t)(row0 + r) * 1024 + kt * 32 + c0c * 8;
            CP16(base + so,        (const char*)(A + go));
            CP16(base + 8192 + so, (const char*)(A + MSZ + go));
        }
    };
    auto preloadB = [&](int kt, uint32_t base) {
        #pragma unroll
        for (int q = 0; q < 2; q++) {
            int r = r0c + q * 64;
            uint32_t so = swz(r, c0c);
            size_t gb = (size_t)(col0 + r) * 1024 + kt * 32 + c0c * 8;
            CP16(base + 16384 + so, (const char*)(B + gb));
            CP16(base + 24576 + so, (const char*)(B + MSZ + gb));
        }
        CP_COMMIT();
    };

    // mode: 0 = prefetch kt+2, 1 = no prefetch (wait1), 2 = last (wait0)
    auto step = [&](int kt, uint32_t ab, uint32_t pb, int mode) {
        if (mode == 2) CP_WAIT0(); else CP_WAIT1();
        __syncthreads();
        #pragma unroll
        for (int kh = 0; kh < 2; kh++) {
            uint32_t bhf[2][4], blf[2][4];
            #pragma unroll
            for (int nj = 0; nj < 2; nj++) {
                int br = wn + nj * 16 + (lane & 15);
                uint32_t bd = ab + 16384 + swz(br, kh * 2 + (lane >> 4));
                LDSM4(bhf[nj], bd);
                LDSM4(blf[nj], bd + 8192);
            }
            if (mode == 0) {
                if (kh == 0) preloadA(kt + 2, pb);
                else         preloadB(kt + 2, pb);
            }
            // A-fragment addresses: hi plane at +0, lo plane at +8192
            auto adA = [&](int mi) {
                int ar = wm + mi * 16 + (lane & 15);
                return ab + swz(ar, kh * 2 + (lane >> 4));
            };
            uint32_t afA[4], afB[4];
            LDSM4(afA, adA(0));                       // ah(0)
            // ---- hi pass: cur × bhf, cur × blf (8 MMAs per mi) ----
            #pragma unroll
            for (int mi = 0; mi < 4; mi++) {
                uint32_t* cur = (mi & 1) ? afB : afA;
                uint32_t* nxt = (mi & 1) ? afA : afB;
                if (mi < 3) LDSM4(nxt, adA(mi + 1));          // ah(mi+1)
                else        LDSM4(nxt, adA(0) + 8192);        // al(0) prefetch
                #pragma unroll
                for (int ni = 0; ni < 4; ni++) {
                    int g = ni >> 1, w = ni & 1;
                    MMA16816(acc[mi][ni], cur, bhf[g][w], bhf[g][2 + w]);   // Ah*Bh
                }
                #pragma unroll
                for (int ni = 0; ni < 4; ni++) {
                    int g = ni >> 1, w = ni & 1;
                    MMA16816(acc[mi][ni], cur, blf[g][w], blf[g][2 + w]);   // Ah*Bl
                }
            }
            // after hi pass: al(0) sits in afA (loaded at mi==3 into nxt==afA)
            // ---- lo pass: cur × bhf (4 MMAs per mi) ----
            #pragma unroll
            for (int mi = 0; mi < 4; mi++) {
                uint32_t* cur = (mi & 1) ? afB : afA;
                uint32_t* nxt = (mi & 1) ? afA : afB;
                if (mi < 3) LDSM4(nxt, adA(mi + 1) + 8192);   // al(mi+1)
                #pragma unroll
                for (int ni = 0; ni < 4; ni++) {
                    int g = ni >> 1, w = ni & 1;
                    MMA16816(acc[mi][ni], cur, bhf[g][w], bhf[g][2 + w]);   // Al*Bh
                }
            }
        }
    };

    const uint32_t s0 = sm0, s1 = sm0 + STAGE_SZ, s2 = sm0 + 2 * STAGE_SZ;
    preloadA(0, s0); preloadB(0, s0);
    preloadA(1, s1); preloadB(1, s1);

    for (int ktb = 0; ktb < 30; ktb += 3) {
        step(ktb,     s0, s2, 0);
        step(ktb + 1, s1, s0, 0);
        step(ktb + 2, s2, s1, 0);
    }
    step(30, s0, s2, 1);
    step(31, s1, s0, 2);

    // ---- epilogue ----
    __syncthreads();   // smem reuse for transpose staging
    uint32_t* tb_h = (uint32_t*)dsm;          // [128][65] packed bf16x2
    uint32_t* tb_l = tb_h + 128 * 65;

    int rl = lane >> 2, cl = (lane & 3) * 2;
    #pragma unroll
    for (int mi = 0; mi < 4; mi++) {
        #pragma unroll
        for (int ni = 0; ni < 4; ni++) {
            int r1 = wm + mi * 16 + rl;
            int cc = wn + ni * 8 + cl;
            size_t rA = (size_t)(row0 + r1) * 1024 + col0 + cc;
            size_t rB = rA + 8 * 1024;
            float v0 = acc[mi][ni][0], v1 = acc[mi][ni][1];
            float v2 = acc[mi][ni][2], v3 = acc[mi][ni][3];
            if (Add) {
                uint32_t qh = *(const uint32_t*)(Add + rA), ql = *(const uint32_t*)(Add + MSZ + rA);
                v0 += bf_lo(qh) + bf_lo(ql);  v1 += bf_hi(qh) + bf_hi(ql);
                uint32_t rh = *(const uint32_t*)(Add + rB), rlq = *(const uint32_t*)(Add + MSZ + rB);
                v2 += bf_lo(rh) + bf_lo(rlq); v3 += bf_hi(rh) + bf_hi(rlq);
            }
            bf16 h0, l0, h1, l1;
            split_bf16(v0, h0, l0); split_bf16(v1, h1, l1);
            uint32_t ohA = pack2(h0, h1), olA = pack2(l0, l1);
            split_bf16(v2, h0, l0); split_bf16(v3, h1, l1);
            uint32_t ohB = pack2(h0, h1), olB = pack2(l0, l1);
            *(uint32_t*)(C + rA) = ohA;  *(uint32_t*)(C + MSZ + rA) = olA;
            *(uint32_t*)(C + rB) = ohB;  *(uint32_t*)(C + MSZ + rB) = olB;
            if (T) {
                tb_h[r1 * 65 + (cc >> 1)] = ohA;  tb_l[r1 * 65 + (cc >> 1)] = olA;
                tb_h[(r1 + 8) * 65 + (cc >> 1)] = ohB;  tb_l[(r1 + 8) * 65 + (cc >> 1)] = olB;
            }
        }
    }

    if (T) {
        __syncthreads();
        int c = tid >> 1, r0 = (tid & 1) * 64;
        const bf16* b16;
        size_t to = (size_t)(col0 + c) * 1024 + row0 + r0;
        b16 = (const bf16*)tb_h;
        {
            uint32_t o[32];
            #pragma unroll
            for (int r = 0; r < 64; r += 2)
                o[r >> 1] = pack2(b16[(r0 + r) * 130 + c], b16[(r0 + r + 1) * 130 + c]);
            #pragma unroll
            for (int w = 0; w < 8; w++)
                *(uint4*)(T + to + w * 8) = make_uint4(o[w*4], o[w*4+1], o[w*4+2], o[w*4+3]);
        }
        b16 = (const bf16*)tb_l;
        {
            uint32_t o[32];
            #pragma unroll
            for (int r = 0; r < 64; r += 2)
                o[r >> 1] = pack2(b16[(r0 + r) * 130 + c], b16[(r0 + r + 1) * 130 + c]);
            #pragma unroll
            for (int w = 0; w < 8; w++)
                *(uint4*)(T + MSZ + to + w * 8) = make_uint4(o[w*4], o[w*4+1], o[w*4+2], o[w*4+3]);
        }
    }
}

// dual-task GEMM kernel: z < nz0 -> set 0, else set 1 (batch index z - nz0)
__global__ void __launch_bounds__(256, 2) k_mma(const bf16* __restrict__ A0, const bf16* __restrict__ B0,
                                                bf16* __restrict__ C0, const bf16* __restrict__ Add0,
                                                bf16* __restrict__ T0,
                                                const bf16* __restrict__ A1, const bf16* __restrict__ B1,
                                                bf16* __restrict__ C1, const bf16* __restrict__ Add1,
                                                bf16* __restrict__ T1,
                                                int nz0) {
    extern __shared__ __align__(16) char dsm[];
    int z = blockIdx.z;
    const bf16 *A, *B, *Add; bf16 *C, *T; int zb;
    if (z < nz0) { A = A0; B = B0; C = C0; Add = Add0; T = T0; zb = z; }
    else         { A = A1; B = B1; C = C1; Add = Add1; T = T1; zb = z - nz0; }
    mma_body(A, B, C, Add, T, dsm, zb, blockIdx.x, blockIdx.y, threadIdx.x);
}

// ---------------- G[b,l,t] = sum_d C[b,l,d] * B[b,t,d] ----------------
__global__ void __launch_bounds__(256) k_gmat(const float* __restrict__ Cm,
                                              const float* __restrict__ Bm) {
    __shared__ float Cs[64][65];
    __shared__ float Bs2[64][65];
    int b = blockIdx.z;
    int t0 = blockIdx.x * 64, l0 = blockIdx.y * 64;
    int tid = threadIdx.x;
    #pragma unroll
    for (int q = 0; q < 4; q++) {
        int idx = tid + q * 256;
        int r = idx >> 4, c4 = (idx & 15) * 4;
        float4 v = *(const float4*)(Cm + ((size_t)(b * LG + l0 + r)) * DS + c4);
        Cs[r][c4] = v.x; Cs[r][c4 + 1] = v.y; Cs[r][c4 + 2] = v.z; Cs[r][c4 + 3] = v.w;
        float4 w = *(const float4*)(Bm + ((size_t)(b * LG + t0 + r)) * DS + c4);
        Bs2[r][c4] = w.x; Bs2[r][c4 + 1] = w.y; Bs2[r][c4 + 2] = w.z; Bs2[r][c4 + 3] = w.w;
    }
    __syncthreads();
    int tx = tid & 15, ty = tid >> 4;
    float acc[4][4] = {};
    for (int d = 0; d < 64; d++) {
        float c[4], bb[4];
        #pragma unroll
        for (int i = 0; i < 4; i++) c[i] = Cs[ty * 4 + i][d];
        #pragma unroll
        for (int j = 0; j < 4; j++) bb[j] = Bs2[tx * 4 + j][d];
        #pragma unroll
        for (int i = 0; i < 4; i++)
            #pragma unroll
            for (int j = 0; j < 4; j++)
                acc[i][j] += c[i] * bb[j];
    }
    #pragma unroll
    for (int i = 0; i < 4; i++)
        #pragma unroll
        for (int j = 0; j < 4; j++)
            g_G[((size_t)b * LG + l0 + ty * 4 + i) * LG + t0 + tx * 4 + j] = acc[i][j];
}

// ---------------- y = ((Lmat . G) * dt_self_t) @ x_head + x ----------------
__global__ void __launch_bounds__(256) k_final(const bf16* __restrict__ O,
                                               const float* __restrict__ x,
                                               const float* __restrict__ Dp,
                                               float* __restrict__ out) {
    int bh = blockIdx.z;
    int b = bh >> 3, h = bh & 7;
    int l0 = blockIdx.x * 64;
    size_t boff = (size_t)bh << 20;
    const float* Gb = g_G + (size_t)b * LG * LG;

    __shared__ float Os[64][65];
    __shared__ float Gs[64][65];
    __shared__ float xs[64][17];
    __shared__ float ws[64];

    int tid = threadIdx.x;
    int l = tid & 63;
    int d0 = (tid >> 6) * 4;
    float acc[4] = {0.f, 0.f, 0.f, 0.f};

    for (int t0 = 0; t0 < LG; t0 += 64) {
        #pragma unroll
        for (int q = 0; q < 2; q++) {
            int idx = tid + q * 256;
            int r = idx >> 3, c8 = (idx & 7) * 8;
            uint4 qh = *(const uint4*)(O + boff + (size_t)(l0 + r) * LG + t0 + c8);
            uint4 ql = *(const uint4*)(O + MSZ + boff + (size_t)(l0 + r) * LG + t0 + c8);
            const uint32_t* hh = (const uint32_t*)&qh;
            const uint32_t* ll = (const uint32_t*)&ql;
            #pragma unroll
            for (int p = 0; p < 4; p++) {
                Os[r][c8 + 2 * p]     = bf_lo(hh[p]) + bf_lo(ll[p]);
                Os[r][c8 + 2 * p + 1] = bf_hi(hh[p]) + bf_hi(ll[p]);
            }
        }
        #pragma unroll
        for (int q = 0; q < 4; q++) {
            int idx = tid + q * 256;
            int r = idx >> 4, c4 = (idx & 15) * 4;
            float4 g = *(const float4*)(Gb + (size_t)(l0 + r) * LG + t0 + c4);
            Gs[r][c4] = g.x; Gs[r][c4 + 1] = g.y; Gs[r][c4 + 2] = g.z; Gs[r][c4 + 3] = g.w;
        }
        {
            int t = tid >> 2, d4 = (tid & 3) * 4;
            float4 v = *(const float4*)(x + (size_t)(b * LG + t0 + t) * 128 + h * HD + d4);
            xs[t][d4] = v.x; xs[t][d4 + 1] = v.y; xs[t][d4 + 2] = v.z; xs[t][d4 + 3] = v.w;
        }
        if (tid < 64) ws[tid] = g_w[h * NN_NODES + b * LG + t0 + tid];
        __syncthreads();
        #pragma unroll 8
        for (int tt = 0; tt < 64; tt++) {
            float a = Os[l][tt] * Gs[l][tt] * ws[tt];
            #pragma unroll
            for (int j = 0; j < 4; j++) acc[j] += a * xs[tt][d0 + j];
        }
        __syncthreads();
    }

    float dh = Dp[h];
    int n = b * LG + l0 + l;
    #pragma unroll
    for (int j = 0; j < 4; j++) {
        float xv = x[(size_t)n * 128 + h * HD + d0 + j];
        out[(size_t)n * 128 + (d0 + j) * NH + h] = acc[j] + xv * dh;
    }
}

// ---------------- host launcher ----------------
extern "C" void kernel_launch(void* const* d_in, const int* in_sizes, int n_in,
                              void* d_out, int out_size) {
    const float* x   = (const float*)d_in[0];
    const float* Bm  = (const float*)d_in[1];
    const float* Cm  = (const float*)d_in[2];
    const float* dt  = (const float*)d_in[3];
    const float* dtb = (const float*)d_in[4];
    const float* Dp  = (const float*)d_in[5];
    const int*   ei  = (const int*)  d_in[6];
    float* out = (float*)d_out;

    float* S;
    cudaGetSymbolAddress((void**)&S, g_S);
    bf16 *la, *lat, *lb, *lbt, *oa, *ob;
    cudaGetSymbolAddress((void**)&la,  g_La);
    cudaGetSymbolAddress((void**)&lat, g_LaT);
    cudaGetSymbolAddress((void**)&lb,  g_Lb);
    cudaGetSymbolAddress((void**)&lbt, g_LbT);
    cudaGetSymbolAddress((void**)&oa,  g_Oa);
    cudaGetSymbolAddress((void**)&ob,  g_Ob);

    cudaFuncSetAttribute(k_mma, cudaFuncAttributeMaxDynamicSharedMemorySize, MMA_SMEM);

    k_zeronode<<<2048, 256>>>(dt, dtb, S);
    k_scatter<<<(NE * NH) / 256, 256>>>(ei);
    k_normprep<<<dim3(32, 64), 256>>>();
    // after normprep: la = M, lat = M^T, oa = I+M

    // phase 0: lb = M^2 (A=la, B=lat), transposed copy into lbt
    k_mma<<<dim3(8, 8, NB), 256, MMA_SMEM>>>(la, lat, lb, nullptr, lbt,
                                             la, lat, lb, nullptr, lbt, NB);

    // phases 1..4: combined  { ob = oa@lb + oa  |  la' = lb@lb (+ transpose) }
    for (int i = 0; i < 4; i++) {
        k_mma<<<dim3(8, 8, 2 * NB), 256, MMA_SMEM>>>(oa, lbt, ob, oa, nullptr,
                                                     lb, lbt, la, nullptr, lat, NB);
        bf16* t;
        t = oa; oa = ob;  ob = t;     // out advanced
        t = la; la = lb;  lb = t;     // lb now holds the new square
        t = lat; lat = lbt; lbt = t;
    }

    // phase 5: final out update  ob = oa@lb(M^32) + oa
    k_mma<<<dim3(8, 8, NB), 256, MMA_SMEM>>>(oa, lbt, ob, oa, nullptr,
                                             oa, lbt, ob, oa, nullptr, NB);

    k_gmat<<<dim3(16, 16, NG), 256>>>(Cm, Bm);
    k_final<<<dim3(16, 1, NB), 256>>>(ob, x, Dp, out);
}

// round 13
// speedup vs baseline: 1.0381x; 1.0381x over previous
#include <cuda_runtime.h>
#include <cuda_bf16.h>
#include <stdint.h>
#include <math.h>

#define NG 8
#define LG 1024
#define NH 8
#define HD 16
#define DS 64
#define NB 64
#define NE 131072
#define NN_NODES 8192
#define MSZ (64ULL * 1024 * 1024)

typedef __nv_bfloat16 bf16;

__device__ float g_S[MSZ];
__device__ float g_G[8ULL * 1024 * 1024];
// each logical matrix: hi plane at [0, MSZ), lo plane at [MSZ, 2*MSZ)
__device__ bf16 g_La[2 * MSZ], g_LaT[2 * MSZ];
__device__ bf16 g_Lb[2 * MSZ], g_LbT[2 * MSZ];
__device__ bf16 g_Oa[2 * MSZ], g_Ob[2 * MSZ];
__device__ float g_e0[NH * NN_NODES];
__device__ float g_e1[NH * NN_NODES];
__device__ float g_dummy[NH * NN_NODES];
__device__ float g_w[NH * NN_NODES];

// ---------------- helpers ----------------
__device__ __forceinline__ uint32_t smem_u32(const void* p) {
    uint32_t a;
    asm("{ .reg .u64 t; cvta.to.shared.u64 t, %1; cvt.u32.u64 %0, t; }" : "=r"(a) : "l"(p));
    return a;
}
#define CP16(dst, src) asm volatile("cp.async.cg.shared.global [%0], [%1], 16;" :: "r"(dst), "l"(src) : "memory")
#define CP_COMMIT()    asm volatile("cp.async.commit_group;" ::: "memory")
#define CP_WAIT1()     asm volatile("cp.async.wait_group 1;" ::: "memory")
#define CP_WAIT0()     asm volatile("cp.async.wait_group 0;" ::: "memory")

#define LDSM4(r, addr) \
    asm volatile("ldmatrix.sync.aligned.m8n8.x4.shared.b16 {%0,%1,%2,%3}, [%4];" \
        : "=r"((r)[0]), "=r"((r)[1]), "=r"((r)[2]), "=r"((r)[3]) : "r"(addr))

#define MMA16816(d, a, b0, b1) \
    asm volatile("mma.sync.aligned.m16n8k16.row.col.f32.bf16.bf16.f32 " \
        "{%0,%1,%2,%3}, {%4,%5,%6,%7}, {%8,%9}, {%0,%1,%2,%3};" \
        : "+f"((d)[0]), "+f"((d)[1]), "+f"((d)[2]), "+f"((d)[3]) \
        : "r"((a)[0]), "r"((a)[1]), "r"((a)[2]), "r"((a)[3]), "r"(b0), "r"(b1))

__device__ __forceinline__ float bf_lo(uint32_t u) { return __bfloat162float(__ushort_as_bfloat16((unsigned short)(u & 0xFFFF))); }
__device__ __forceinline__ float bf_hi(uint32_t u) { return __bfloat162float(__ushort_as_bfloat16((unsigned short)(u >> 16))); }
__device__ __forceinline__ void split_bf16(float v, bf16& h, bf16& l) {
    h = __float2bfloat16(v);
    l = __float2bfloat16(v - __bfloat162float(h));
}
__device__ __forceinline__ uint32_t pack2(bf16 a, bf16 b) {
    return ((uint32_t)__bfloat16_as_ushort(b) << 16) | __bfloat16_as_ushort(a);
}
__device__ __forceinline__ float softplusf(float x) { return (x > 15.f) ? x : log1pf(expf(x)); }

// swizzled offset inside a 128-row x 64B operand block: row r, 16B-chunk c (0..3)
__device__ __forceinline__ uint32_t swz(int r, int c) {
    return (uint32_t)(r * 64 + ((c ^ (r >> 1)) & 3) * 16);
}

// ---------------- fused zero + per-node prep ----------------
__global__ void k_zeronode(const float* __restrict__ dt, const float* __restrict__ dtb,
                           float* __restrict__ S) {
    int gid = blockIdx.x * blockDim.x + threadIdx.x;
    if (gid < NN_NODES * NH) {
        int n = gid >> 3, h = gid & 7;
        float b = dtb[h];
        const float* row = dt + (size_t)n * (NH * 4) + h * 4;
        g_e0[h * NN_NODES + n] = -softplusf(row[0] + b);
        g_e1[h * NN_NODES + n] = -softplusf(row[1] + b);
        g_dummy[h * NN_NODES + n] = expf(-softplusf(row[2] + b));
        g_w[h * NN_NODES + n] = row[3];
    }
    size_t i = (size_t)gid * 4;
    size_t st = (size_t)gridDim.x * blockDim.x * 4;
    float4 z = make_float4(0.f, 0.f, 0.f, 0.f);
    for (; i < MSZ; i += st) *(float4*)(S + i) = z;
}

// ---------------- edge scatter ----------------
__global__ void k_scatter(const int* __restrict__ ei) {
    int idx = blockIdx.x * blockDim.x + threadIdx.x;
    if (idx >= NE * NH) return;
    int e = idx >> 3, h = idx & 7;
    int s = ei[e], d = ei[NE + e];
    int b = s >> 10, sl = s & 1023, dl = d & 1023;
    float v = expf(0.5f * (g_e0[h * NN_NODES + s] + g_e1[h * NN_NODES + d]));
    atomicAdd(&g_S[(((size_t)(b * NH + h)) * LG + sl) * LG + dl], v);
}

// ---------------- fused norm + prep ----------------
__global__ void __launch_bounds__(256) k_normprep() {
    __shared__ float snrm[32];
    __shared__ float t[32][33];
    int bh = blockIdx.y;
    int j0 = blockIdx.x * 32;
    int b = bh >> 3, h = bh & 7;
    size_t off = (size_t)bh << 20;
    int tid = threadIdx.x;
    int wid = tid >> 5, lane = tid & 31;

    #pragma unroll
    for (int rr = 0; rr < 4; rr++) {
        int jj = wid * 4 + rr;
        const float* row = g_S + off + (size_t)(j0 + jj) * LG;
        float s = 0.f;
        for (int i = lane; i < LG; i += 32) s += row[i];
        #pragma unroll
        for (int o = 16; o; o >>= 1) s += __shfl_xor_sync(0xFFFFFFFFu, s, o);
        if (lane == 0)
            snrm[jj] = 1.f / (s + g_dummy[h * NN_NODES + b * LG + j0 + jj] + 0.1f);
    }
    __syncthreads();

    int tx = tid & 31, ty = tid >> 5;   // (32, 8)
    for (int i0 = 0; i0 < LG; i0 += 32) {
        #pragma unroll
        for (int k = 0; k < 4; k++) {
            int jj = ty + k * 8;
            float v = g_S[off + (size_t)(j0 + jj) * LG + i0 + tx];
            t[jj][tx] = v;
            float mt = v * snrm[jj];
            size_t o = off + (size_t)(j0 + jj) * LG + i0 + tx;
            bf16 hh, ll; split_bf16(mt, hh, ll);
            g_LaT[o] = hh; g_LaT[MSZ + o] = ll;
        }
        __syncthreads();
        #pragma unroll
        for (int k = 0; k < 4; k++) {
            int i = i0 + ty + k * 8;
            int j = j0 + tx;
            float v = t[tx][ty + k * 8] * snrm[tx];
            size_t o = off + (size_t)i * LG + j;
            bf16 hh, ll; split_bf16(v, hh, ll);
            g_La[o] = hh; g_La[MSZ + o] = ll;
            float w = v + ((i == j) ? 1.f : 0.f);
            split_bf16(w, hh, ll);
            g_Oa[o] = hh; g_Oa[MSZ + o] = ll;
        }
        __syncthreads();
    }
}

// ---------------- HMMA batched GEMM body: C = A@B (+Add), split bf16 x3 ----------------
// Tile 128x128, warp tile 64x32, KC=32, 3-stage, XOR-swizzled 64B rows, 1 barrier/kt.
// kh0 B-fragments hoisted across the step boundary (loaded at tail of previous step).
#define STAGE_SZ 32768
#define MMA_SMEM (3 * STAGE_SZ)

__device__ __forceinline__ void mma_body(const bf16* __restrict__ A,
                                         const bf16* __restrict__ B,
                                         bf16* __restrict__ C,
                                         const bf16* __restrict__ Add,
                                         bf16* __restrict__ T,
                                         char* dsm, int zb,
                                         int bx, int by, int tid) {
    size_t moff = (size_t)zb << 20;
    A += moff; B += moff; C += moff;
    if (Add) Add += moff;
    if (T) T += moff;
    int row0 = by * 128, col0 = bx * 128;

    uint32_t sm0 = smem_u32(dsm);
    int wid = tid >> 5, lane = tid & 31;
    int wm = (wid >> 2) * 64, wn = (wid & 3) * 32;

    float acc[4][4][4];
    #pragma unroll
    for (int i = 0; i < 4; i++)
        #pragma unroll
        for (int j = 0; j < 4; j++)
            #pragma unroll
            for (int k = 0; k < 4; k++) acc[i][j][k] = 0.f;

    const int r0c = tid >> 2, c0c = tid & 3;

    auto preloadA = [&](int kt, uint32_t base) {
        #pragma unroll
        for (int q = 0; q < 2; q++) {
            int r = r0c + q * 64;
            uint32_t so = swz(r, c0c);
            size_t go = (size_t)(row0 + r) * 1024 + kt * 32 + c0c * 8;
            CP16(base + so,        (const char*)(A + go));
            CP16(base + 8192 + so, (const char*)(A + MSZ + go));
        }
    };
    auto preloadB = [&](int kt, uint32_t base) {
        #pragma unroll
        for (int q = 0; q < 2; q++) {
            int r = r0c + q * 64;
            uint32_t so = swz(r, c0c);
            size_t gb = (size_t)(col0 + r) * 1024 + kt * 32 + c0c * 8;
            CP16(base + 16384 + so, (const char*)(B + gb));
            CP16(base + 24576 + so, (const char*)(B + MSZ + gb));
        }
        CP_COMMIT();
    };

    // persistent B fragments (carried across the step boundary for kh0)
    uint32_t bhf[2][4], blf[2][4];

    auto loadB = [&](uint32_t ab, int kh) {
        #pragma unroll
        for (int nj = 0; nj < 2; nj++) {
            int br = wn + nj * 16 + (lane & 15);
            uint32_t bd = ab + 16384 + swz(br, kh * 2 + (lane >> 4));
            LDSM4(bhf[nj], bd);
            LDSM4(blf[nj], bd + 8192);
        }
    };

    auto computeA = [&](uint32_t ab, int kh) {
        #pragma unroll
        for (int mi = 0; mi < 4; mi++) {
            uint32_t ah[4], al[4];
            int ar = wm + mi * 16 + (lane & 15);
            uint32_t ad = ab + swz(ar, kh * 2 + (lane >> 4));
            LDSM4(ah, ad);
            LDSM4(al, ad + 8192);
            #pragma unroll
            for (int ni = 0; ni < 4; ni++) {
                int g = ni >> 1, w = ni & 1;
                MMA16816(acc[mi][ni], ah, bhf[g][w], bhf[g][2 + w]);   // Ah*Bh
            }
            #pragma unroll
            for (int ni = 0; ni < 4; ni++) {
                int g = ni >> 1, w = ni & 1;
                MMA16816(acc[mi][ni], ah, blf[g][w], blf[g][2 + w]);   // Ah*Bl
            }
            #pragma unroll
            for (int ni = 0; ni < 4; ni++) {
                int g = ni >> 1, w = ni & 1;
                MMA16816(acc[mi][ni], al, bhf[g][w], bhf[g][2 + w]);   // Al*Bh
            }
        }
    };

    // mode: 0 = prefetch kt+2 + normal tail; 1 = no prefetch, tail WAIT0; 2 = last, no tail
    auto step = [&](int kt, uint32_t ab, uint32_t nb, uint32_t pb, int mode) {
        // entry: kh0 B-frags for kt already in regs; stage ab data visible
        if (mode == 0) preloadA(kt + 2, pb);
        computeA(ab, 0);
        loadB(ab, 1);
        if (mode == 0) preloadB(kt + 2, pb);   // commit
        computeA(ab, 1);
        if (mode != 2) {
            if (mode == 1) CP_WAIT0(); else CP_WAIT1();   // own copies of G(kt+1) done
            __syncthreads();                              // visibility + stage-reuse protection
            loadB(nb, 0);                                 // next kt kh0 B-frags
        }
    };

    const uint32_t s0 = sm0, s1 = sm0 + STAGE_SZ, s2 = sm0 + 2 * STAGE_SZ;
    preloadA(0, s0); preloadB(0, s0);
    preloadA(1, s1); preloadB(1, s1);
    CP_WAIT1();          // own G0 copies done
    __syncthreads();     // all G0 copies visible
    loadB(s0, 0);        // kt0 kh0 B-frags

    for (int ktb = 0; ktb < 30; ktb += 3) {
        step(ktb,     s0, s1, s2, 0);
        step(ktb + 1, s1, s2, s0, 0);
        step(ktb + 2, s2, s0, s1, 0);
    }
    step(30, s0, s1, s2, 1);
    step(31, s1, s2, s0, 2);

    // ---- epilogue ----
    __syncthreads();   // smem reuse for transpose staging
    uint32_t* tb_h = (uint32_t*)dsm;          // [128][65] packed bf16x2
    uint32_t* tb_l = tb_h + 128 * 65;

    int rl = lane >> 2, cl = (lane & 3) * 2;
    #pragma unroll
    for (int mi = 0; mi < 4; mi++) {
        #pragma unroll
        for (int ni = 0; ni < 4; ni++) {
            int r1 = wm + mi * 16 + rl;
            int cc = wn + ni * 8 + cl;
            size_t rA = (size_t)(row0 + r1) * 1024 + col0 + cc;
            size_t rB = rA + 8 * 1024;
            float v0 = acc[mi][ni][0], v1 = acc[mi][ni][1];
            float v2 = acc[mi][ni][2], v3 = acc[mi][ni][3];
            if (Add) {
                uint32_t qh = *(const uint32_t*)(Add + rA), ql = *(const uint32_t*)(Add + MSZ + rA);
                v0 += bf_lo(qh) + bf_lo(ql);  v1 += bf_hi(qh) + bf_hi(ql);
                uint32_t rh = *(const uint32_t*)(Add + rB), rlq = *(const uint32_t*)(Add + MSZ + rB);
                v2 += bf_lo(rh) + bf_lo(rlq); v3 += bf_hi(rh) + bf_hi(rlq);
            }
            bf16 h0, l0, h1, l1;
            split_bf16(v0, h0, l0); split_bf16(v1, h1, l1);
            uint32_t ohA = pack2(h0, h1), olA = pack2(l0, l1);
            split_bf16(v2, h0, l0); split_bf16(v3, h1, l1);
            uint32_t ohB = pack2(h0, h1), olB = pack2(l0, l1);
            *(uint32_t*)(C + rA) = ohA;  *(uint32_t*)(C + MSZ + rA) = olA;
            *(uint32_t*)(C + rB) = ohB;  *(uint32_t*)(C + MSZ + rB) = olB;
            if (T) {
                tb_h[r1 * 65 + (cc >> 1)] = ohA;  tb_l[r1 * 65 + (cc >> 1)] = olA;
                tb_h[(r1 + 8) * 65 + (cc >> 1)] = ohB;  tb_l[(r1 + 8) * 65 + (cc >> 1)] = olB;
            }
        }
    }

    if (T) {
        __syncthreads();
        int c = tid >> 1, r0 = (tid & 1) * 64;
        const bf16* b16;
        size_t to = (size_t)(col0 + c) * 1024 + row0 + r0;
        b16 = (const bf16*)tb_h;
        {
            uint32_t o[32];
            #pragma unroll
            for (int r = 0; r < 64; r += 2)
                o[r >> 1] = pack2(b16[(r0 + r) * 130 + c], b16[(r0 + r + 1) * 130 + c]);
            #pragma unroll
            for (int w = 0; w < 8; w++)
                *(uint4*)(T + to + w * 8) = make_uint4(o[w*4], o[w*4+1], o[w*4+2], o[w*4+3]);
        }
        b16 = (const bf16*)tb_l;
        {
            uint32_t o[32];
            #pragma unroll
            for (int r = 0; r < 64; r += 2)
                o[r >> 1] = pack2(b16[(r0 + r) * 130 + c], b16[(r0 + r + 1) * 130 + c]);
            #pragma unroll
            for (int w = 0; w < 8; w++)
                *(uint4*)(T + MSZ + to + w * 8) = make_uint4(o[w*4], o[w*4+1], o[w*4+2], o[w*4+3]);
        }
    }
}

// dual-task GEMM kernel: z < nz0 -> set 0, else set 1 (batch index z - nz0)
__global__ void __launch_bounds__(256, 2) k_mma(const bf16* __restrict__ A0, const bf16* __restrict__ B0,
                                                bf16* __restrict__ C0, const bf16* __restrict__ Add0,
                                                bf16* __restrict__ T0,
                                                const bf16* __restrict__ A1, const bf16* __restrict__ B1,
                                                bf16* __restrict__ C1, const bf16* __restrict__ Add1,
                                                bf16* __restrict__ T1,
                                                int nz0) {
    extern __shared__ __align__(16) char dsm[];
    int z = blockIdx.z;
    const bf16 *A, *B, *Add; bf16 *C, *T; int zb;
    if (z < nz0) { A = A0; B = B0; C = C0; Add = Add0; T = T0; zb = z; }
    else         { A = A1; B = B1; C = C1; Add = Add1; T = T1; zb = z - nz0; }
    mma_body(A, B, C, Add, T, dsm, zb, blockIdx.x, blockIdx.y, threadIdx.x);
}

// ---------------- G[b,l,t] = sum_d C[b,l,d] * B[b,t,d] ----------------
__global__ void __launch_bounds__(256) k_gmat(const float* __restrict__ Cm,
                                              const float* __restrict__ Bm) {
    __shared__ float Cs[64][65];
    __shared__ float Bs2[64][65];
    int b = blockIdx.z;
    int t0 = blockIdx.x * 64, l0 = blockIdx.y * 64;
    int tid = threadIdx.x;
    #pragma unroll
    for (int q = 0; q < 4; q++) {
        int idx = tid + q * 256;
        int r = idx >> 4, c4 = (idx & 15) * 4;
        float4 v = *(const float4*)(Cm + ((size_t)(b * LG + l0 + r)) * DS + c4);
        Cs[r][c4] = v.x; Cs[r][c4 + 1] = v.y; Cs[r][c4 + 2] = v.z; Cs[r][c4 + 3] = v.w;
        float4 w = *(const float4*)(Bm + ((size_t)(b * LG + t0 + r)) * DS + c4);
        Bs2[r][c4] = w.x; Bs2[r][c4 + 1] = w.y; Bs2[r][c4 + 2] = w.z; Bs2[r][c4 + 3] = w.w;
    }
    __syncthreads();
    int tx = tid & 15, ty = tid >> 4;
    float acc[4][4] = {};
    for (int d = 0; d < 64; d++) {
        float c[4], bb[4];
        #pragma unroll
        for (int i = 0; i < 4; i++) c[i] = Cs[ty * 4 + i][d];
        #pragma unroll
        for (int j = 0; j < 4; j++) bb[j] = Bs2[tx * 4 + j][d];
        #pragma unroll
        for (int i = 0; i < 4; i++)
            #pragma unroll
            for (int j = 0; j < 4; j++)
                acc[i][j] += c[i] * bb[j];
    }
    #pragma unroll
    for (int i = 0; i < 4; i++)
        #pragma unroll
        for (int j = 0; j < 4; j++)
            g_G[((size_t)b * LG + l0 + ty * 4 + i) * LG + t0 + tx * 4 + j] = acc[i][j];
}

// ---------------- y = ((Lmat . G) * dt_self_t) @ x_head + x ----------------
__global__ void __launch_bounds__(256) k_final(const bf16* __restrict__ O,
                                               const float* __restrict__ x,
                                               const float* __restrict__ Dp,
                                               float* __restrict__ out) {
    int bh = blockIdx.z;
    int b = bh >> 3, h = bh & 7;
    int l0 = blockIdx.x * 64;
    size_t boff = (size_t)bh << 20;
    const float* Gb = g_G + (size_t)b * LG * LG;

    __shared__ float Os[64][65];
    __shared__ float Gs[64][65];
    __shared__ float xs[64][17];
    __shared__ float ws[64];

    int tid = threadIdx.x;
    int l = tid & 63;
    int d0 = (tid >> 6) * 4;
    float acc[4] = {0.f, 0.f, 0.f, 0.f};

    for (int t0 = 0; t0 < LG; t0 += 64) {
        #pragma unroll
        for (int q = 0; q < 2; q++) {
            int idx = tid + q * 256;
            int r = idx >> 3, c8 = (idx & 7) * 8;
            uint4 qh = *(const uint4*)(O + boff + (size_t)(l0 + r) * LG + t0 + c8);
            uint4 ql = *(const uint4*)(O + MSZ + boff + (size_t)(l0 + r) * LG + t0 + c8);
            const uint32_t* hh = (const uint32_t*)&qh;
            const uint32_t* ll = (const uint32_t*)&ql;
            #pragma unroll
            for (int p = 0; p < 4; p++) {
                Os[r][c8 + 2 * p]     = bf_lo(hh[p]) + bf_lo(ll[p]);
                Os[r][c8 + 2 * p + 1] = bf_hi(hh[p]) + bf_hi(ll[p]);
            }
        }
        #pragma unroll
        for (int q = 0; q < 4; q++) {
            int idx = tid + q * 256;
            int r = idx >> 4, c4 = (idx & 15) * 4;
            float4 g = *(const float4*)(Gb + (size_t)(l0 + r) * LG + t0 + c4);
            Gs[r][c4] = g.x; Gs[r][c4 + 1] = g.y; Gs[r][c4 + 2] = g.z; Gs[r][c4 + 3] = g.w;
        }
        {
            int t = tid >> 2, d4 = (tid & 3) * 4;
            float4 v = *(const float4*)(x + (size_t)(b * LG + t0 + t) * 128 + h * HD + d4);
            xs[t][d4] = v.x; xs[t][d4 + 1] = v.y; xs[t][d4 + 2] = v.z; xs[t][d4 + 3] = v.w;
        }
        if (tid < 64) ws[tid] = g_w[h * NN_NODES + b * LG + t0 + tid];
        __syncthreads();
        #pragma unroll 8
        for (int tt = 0; tt < 64; tt++) {
            float a = Os[l][tt] * Gs[l][tt] * ws[tt];
            #pragma unroll
            for (int j = 0; j < 4; j++) acc[j] += a * xs[tt][d0 + j];
        }
        __syncthreads();
    }

    float dh = Dp[h];
    int n = b * LG + l0 + l;
    #pragma unroll
    for (int j = 0; j < 4; j++) {
        float xv = x[(size_t)n * 128 + h * HD + d0 + j];
        out[(size_t)n * 128 + (d0 + j) * NH + h] = acc[j] + xv * dh;
    }
}

// ---------------- host launcher ----------------
extern "C" void kernel_launch(void* const* d_in, const int* in_sizes, int n_in,
                              void* d_out, int out_size) {
    const float* x   = (const float*)d_in[0];
    const float* Bm  = (const float*)d_in[1];
    const float* Cm  = (const float*)d_in[2];
    const float* dt  = (const float*)d_in[3];
    const float* dtb = (const float*)d_in[4];
    const float* Dp  = (const float*)d_in[5];
    const int*   ei  = (const int*)  d_in[6];
    float* out = (float*)d_out;

    float* S;
    cudaGetSymbolAddress((void**)&S, g_S);
    bf16 *la, *lat, *lb, *lbt, *oa, *ob;
    cudaGetSymbolAddress((void**)&la,  g_La);
    cudaGetSymbolAddress((void**)&lat, g_LaT);
    cudaGetSymbolAddress((void**)&lb,  g_Lb);
    cudaGetSymbolAddress((void**)&lbt, g_LbT);
    cudaGetSymbolAddress((void**)&oa,  g_Oa);
    cudaGetSymbolAddress((void**)&ob,  g_Ob);

    cudaFuncSetAttribute(k_mma, cudaFuncAttributeMaxDynamicSharedMemorySize, MMA_SMEM);

    k_zeronode<<<2048, 256>>>(dt, dtb, S);
    k_scatter<<<(NE * NH) / 256, 256>>>(ei);
    k_normprep<<<dim3(32, 64), 256>>>();
    // after normprep: la = M, lat = M^T, oa = I+M

    // phase 0: lb = M^2 (A=la, B=lat), transposed copy into lbt
    k_mma<<<dim3(8, 8, NB), 256, MMA_SMEM>>>(la, lat, lb, nullptr, lbt,
                                             la, lat, lb, nullptr, lbt, NB);

    // phases 1..4: combined  { ob = oa@lb + oa  |  la' = lb@lb (+ transpose) }
    for (int i = 0; i < 4; i++) {
        k_mma<<<dim3(8, 8, 2 * NB), 256, MMA_SMEM>>>(oa, lbt, ob, oa, nullptr,
                                                     lb, lbt, la, nullptr, lat, NB);
        bf16* t;
        t = oa; oa = ob;  ob = t;     // out advanced
        t = la; la = lb;  lb = t;     // lb now holds the new square
        t = lat; lat = lbt; lbt = t;
    }

    // phase 5: final out update  ob = oa@lb(M^32) + oa
    k_mma<<<dim3(8, 8, NB), 256, MMA_SMEM>>>(oa, lbt, ob, oa, nullptr,
                                             oa, lbt, ob, oa, nullptr, NB);

    k_gmat<<<dim3(16, 16, NG), 256>>>(Cm, Bm);
    k_final<<<dim3(16, 1, NB), 256>>>(ob, x, Dp, out);
}